// round 2
// baseline (speedup 1.0000x reference)
#include <cuda_runtime.h>
#include <cstdint>

#define M_ROWS 16384
#define IN_F   2048
#define OUT_F  2048

// Exact identity: out[m,n] = rowsum(x[m]) - 2 * sum_{k: w[n,k] < 0} x[m,k]
// (b_weight = sign(sign(w)+0.5) is -1 iff w < 0, else +1 including w == 0).

__device__ unsigned short g_neg_idx[(size_t)OUT_F * IN_F];  // 8 MB scratch
__device__ int            g_neg_cnt[OUT_F];
__device__ unsigned char  g_neg_flag[OUT_F];                // 1 iff cnt > 0
__device__ float          g_rowsum[M_ROWS];

// ---------------------------------------------------------------------------
// K1: fused streaming pass.
//   blocks [0, 256):    weight scan — warp per weight row (8 rows/block).
//                       Ballot-compacted negative-index lists (no atomics).
//   blocks [256, 2304): x rowsums — warp per x row (8 rows/block).
// ---------------------------------------------------------------------------
__global__ void __launch_bounds__(256) prep_kernel(
    const float* __restrict__ x,
    const float* __restrict__ w)
{
    const int warp = threadIdx.x >> 5;
    const int lane = threadIdx.x & 31;
    const unsigned lt_mask = (1u << lane) - 1u;

    if (blockIdx.x < 256) {
        // ---- weight duty: row n, collect indices of negative entries ----
        const int n = blockIdx.x * 8 + warp;
        const float4* wr = reinterpret_cast<const float4*>(w + (size_t)n * IN_F);
        unsigned short* idx = g_neg_idx + (size_t)n * IN_F;
        int cnt = 0;

        #pragma unroll 4
        for (int it = 0; it < 16; it++) {
            const int i4 = it * 32 + lane;
            const float4 v = wr[i4];
            const int kb = i4 * 4;
            unsigned b;
            b = __ballot_sync(0xffffffffu, v.x < 0.0f);
            if (v.x < 0.0f) idx[cnt + __popc(b & lt_mask)] = (unsigned short)(kb + 0);
            cnt += __popc(b);
            b = __ballot_sync(0xffffffffu, v.y < 0.0f);
            if (v.y < 0.0f) idx[cnt + __popc(b & lt_mask)] = (unsigned short)(kb + 1);
            cnt += __popc(b);
            b = __ballot_sync(0xffffffffu, v.z < 0.0f);
            if (v.z < 0.0f) idx[cnt + __popc(b & lt_mask)] = (unsigned short)(kb + 2);
            cnt += __popc(b);
            b = __ballot_sync(0xffffffffu, v.w < 0.0f);
            if (v.w < 0.0f) idx[cnt + __popc(b & lt_mask)] = (unsigned short)(kb + 3);
            cnt += __popc(b);
        }
        if (lane == 0) {
            g_neg_cnt[n]  = cnt;
            g_neg_flag[n] = (cnt > 0) ? 1 : 0;
        }
    } else {
        // ---- x duty: warp computes rowsum of one x row ----
        const int m = (blockIdx.x - 256) * 8 + warp;
        const float4* xr = reinterpret_cast<const float4*>(x + (size_t)m * IN_F);
        float s = 0.0f;
        #pragma unroll
        for (int it = 0; it < 16; it++) {
            const float4 v = xr[it * 32 + lane];
            s += (v.x + v.y) + (v.z + v.w);
        }
        #pragma unroll
        for (int o = 16; o > 0; o >>= 1)
            s += __shfl_xor_sync(0xffffffffu, s, o);
        if (lane == 0) g_rowsum[m] = s;
    }
}

// ---------------------------------------------------------------------------
// K2: write-only output pass. Warp per output row (8 rows/block).
// Flags staged once per block into smem (2 KB); counts/index lists touched
// only for columns with negative weights.
// ---------------------------------------------------------------------------
__global__ void __launch_bounds__(256) out_kernel(
    const float* __restrict__ x,
    float*       __restrict__ out)
{
    __shared__ unsigned char sflag[OUT_F];
    reinterpret_cast<unsigned long long*>(sflag)[threadIdx.x] =
        reinterpret_cast<const unsigned long long*>(g_neg_flag)[threadIdx.x];
    __syncthreads();

    const int warp = threadIdx.x >> 5;
    const int lane = threadIdx.x & 31;
    const int m = blockIdx.x * 8 + warp;

    const float S = g_rowsum[m];
    float4* orow = reinterpret_cast<float4*>(out + (size_t)m * OUT_F);
    const float* xrow = x + (size_t)m * IN_F;

    #pragma unroll
    for (int it = 0; it < 16; it++) {
        const int i4 = it * 32 + lane;
        const int n0 = i4 * 4;
        float4 v = make_float4(S, S, S, S);

        const uchar4 f = *reinterpret_cast<const uchar4*>(sflag + n0);
        if (f.x | f.y | f.z | f.w) {
            if (f.x) {
                float c = 0.0f;
                const int cnt = g_neg_cnt[n0 + 0];
                const unsigned short* id = g_neg_idx + (size_t)(n0 + 0) * IN_F;
                for (int j = 0; j < cnt; j++) c += xrow[id[j]];
                v.x = S - 2.0f * c;
            }
            if (f.y) {
                float c = 0.0f;
                const int cnt = g_neg_cnt[n0 + 1];
                const unsigned short* id = g_neg_idx + (size_t)(n0 + 1) * IN_F;
                for (int j = 0; j < cnt; j++) c += xrow[id[j]];
                v.y = S - 2.0f * c;
            }
            if (f.z) {
                float c = 0.0f;
                const int cnt = g_neg_cnt[n0 + 2];
                const unsigned short* id = g_neg_idx + (size_t)(n0 + 2) * IN_F;
                for (int j = 0; j < cnt; j++) c += xrow[id[j]];
                v.z = S - 2.0f * c;
            }
            if (f.w) {
                float c = 0.0f;
                const int cnt = g_neg_cnt[n0 + 3];
                const unsigned short* id = g_neg_idx + (size_t)(n0 + 3) * IN_F;
                for (int j = 0; j < cnt; j++) c += xrow[id[j]];
                v.w = S - 2.0f * c;
            }
        }
        orow[i4] = v;
    }
}

// ---------------------------------------------------------------------------
// d_in[0] = x [M, IN_F] fp32, d_in[1] = weight [OUT_F, IN_F] fp32.
// d_out = [M, OUT_F] fp32.
// ---------------------------------------------------------------------------
extern "C" void kernel_launch(void* const* d_in, const int* in_sizes, int n_in,
                              void* d_out, int out_size)
{
    const float* x = (const float*)d_in[0];
    const float* w = (const float*)d_in[1];
    float* out = (float*)d_out;

    prep_kernel<<<256 + M_ROWS / 8, 256>>>(x, w);
    out_kernel<<<M_ROWS / 8, 256>>>(x, out);
}

// round 3
// speedup vs baseline: 1.0203x; 1.0203x over previous
#include <cuda_runtime.h>
#include <cstdint>

#define M_ROWS 16384
#define IN_F   2048
#define OUT_F  2048

// Exact identity: out[m,n] = rowsum(x[m]) - 2 * sum_{k: w[n,k] < 0} x[m,k]
// (b_weight = sign(sign(w)+0.5) is -1 iff w < 0, else +1 including w == 0).

__device__ unsigned short g_neg_idx[(size_t)OUT_F * IN_F];  // 8 MB scratch
__device__ int            g_neg_cnt[OUT_F];
__device__ unsigned char  g_neg_flag[OUT_F];                // 1 iff cnt > 0

// ---------------------------------------------------------------------------
// K1: weight scan. Warp per weight row (8 rows/block, 256 blocks).
// Ballot-compacted negative-index lists; flags rewritten every launch.
// ---------------------------------------------------------------------------
__global__ void __launch_bounds__(256) scan_kernel(const float* __restrict__ w)
{
    const int warp = threadIdx.x >> 5;
    const int lane = threadIdx.x & 31;
    const unsigned lt_mask = (1u << lane) - 1u;

    const int n = blockIdx.x * 8 + warp;
    const float4* wr = reinterpret_cast<const float4*>(w + (size_t)n * IN_F);
    unsigned short* idx = g_neg_idx + (size_t)n * IN_F;
    int cnt = 0;

    #pragma unroll 4
    for (int it = 0; it < 16; it++) {
        const int i4 = it * 32 + lane;
        const float4 v = wr[i4];
        const int kb = i4 * 4;
        unsigned b;
        b = __ballot_sync(0xffffffffu, v.x < 0.0f);
        if (v.x < 0.0f) idx[cnt + __popc(b & lt_mask)] = (unsigned short)(kb + 0);
        cnt += __popc(b);
        b = __ballot_sync(0xffffffffu, v.y < 0.0f);
        if (v.y < 0.0f) idx[cnt + __popc(b & lt_mask)] = (unsigned short)(kb + 1);
        cnt += __popc(b);
        b = __ballot_sync(0xffffffffu, v.z < 0.0f);
        if (v.z < 0.0f) idx[cnt + __popc(b & lt_mask)] = (unsigned short)(kb + 2);
        cnt += __popc(b);
        b = __ballot_sync(0xffffffffu, v.w < 0.0f);
        if (v.w < 0.0f) idx[cnt + __popc(b & lt_mask)] = (unsigned short)(kb + 3);
        cnt += __popc(b);
    }
    if (lane == 0) {
        g_neg_cnt[n]  = cnt;
        g_neg_flag[n] = (cnt > 0) ? 1 : 0;
    }
}

// ---------------------------------------------------------------------------
// K2: fused read-reduce-write. Warp per x row (8 rows/block, 2048 blocks).
// No smem staging of x, no block syncs in the hot loop; one syncthreads_or
// dispatches the block between the pure-splat path and the correction path.
// ---------------------------------------------------------------------------
__global__ void __launch_bounds__(256) out_kernel(
    const float* __restrict__ x,
    float*       __restrict__ out)
{
    __shared__ unsigned char sflag[OUT_F];

    // Each thread inspects 8 flag bytes; block-wide OR decides the path.
    const unsigned long long fchunk =
        reinterpret_cast<const unsigned long long*>(g_neg_flag)[threadIdx.x];
    const int any_neg = __syncthreads_or(fchunk != 0ull);
    if (any_neg)
        reinterpret_cast<unsigned long long*>(sflag)[threadIdx.x] = fchunk;
    if (any_neg)
        __syncthreads();

    const int warp = threadIdx.x >> 5;
    const int lane = threadIdx.x & 31;
    const int m = blockIdx.x * 8 + warp;

    const float* xrow = x + (size_t)m * IN_F;
    const float4* xr4 = reinterpret_cast<const float4*>(xrow);
    float4* orow = reinterpret_cast<float4*>(out + (size_t)m * OUT_F);

    // Row sum: 16 vector loads per lane, front-batched for MLP.
    float s0 = 0.0f, s1 = 0.0f;
    #pragma unroll
    for (int it = 0; it < 16; it += 2) {
        const float4 a = xr4[it * 32 + lane];
        const float4 b = xr4[(it + 1) * 32 + lane];
        s0 += (a.x + a.y) + (a.z + a.w);
        s1 += (b.x + b.y) + (b.z + b.w);
    }
    float s = s0 + s1;
    #pragma unroll
    for (int o = 16; o > 0; o >>= 1)
        s += __shfl_xor_sync(0xffffffffu, s, o);
    const float S = s;

    if (!any_neg) {
        // Pure splat: 16 coalesced STG.128 per lane.
        const float4 v = make_float4(S, S, S, S);
        #pragma unroll
        for (int it = 0; it < 16; it++)
            orow[it * 32 + lane] = v;
    } else {
        // General path: per-column correction via gathered x (L2-hot).
        #pragma unroll 4
        for (int it = 0; it < 16; it++) {
            const int i4 = it * 32 + lane;
            const int n0 = i4 * 4;
            float4 v = make_float4(S, S, S, S);
            const uchar4 f = *reinterpret_cast<const uchar4*>(sflag + n0);
            if (f.x | f.y | f.z | f.w) {
                if (f.x) {
                    float c = 0.0f;
                    const int cnt = g_neg_cnt[n0 + 0];
                    const unsigned short* id = g_neg_idx + (size_t)(n0 + 0) * IN_F;
                    for (int j = 0; j < cnt; j++) c += __ldg(xrow + id[j]);
                    v.x = S - 2.0f * c;
                }
                if (f.y) {
                    float c = 0.0f;
                    const int cnt = g_neg_cnt[n0 + 1];
                    const unsigned short* id = g_neg_idx + (size_t)(n0 + 1) * IN_F;
                    for (int j = 0; j < cnt; j++) c += __ldg(xrow + id[j]);
                    v.y = S - 2.0f * c;
                }
                if (f.z) {
                    float c = 0.0f;
                    const int cnt = g_neg_cnt[n0 + 2];
                    const unsigned short* id = g_neg_idx + (size_t)(n0 + 2) * IN_F;
                    for (int j = 0; j < cnt; j++) c += __ldg(xrow + id[j]);
                    v.z = S - 2.0f * c;
                }
                if (f.w) {
                    float c = 0.0f;
                    const int cnt = g_neg_cnt[n0 + 3];
                    const unsigned short* id = g_neg_idx + (size_t)(n0 + 3) * IN_F;
                    for (int j = 0; j < cnt; j++) c += __ldg(xrow + id[j]);
                    v.w = S - 2.0f * c;
                }
            }
            orow[i4] = v;
        }
    }
}

// ---------------------------------------------------------------------------
// d_in[0] = x [M, IN_F] fp32, d_in[1] = weight [OUT_F, IN_F] fp32.
// d_out = [M, OUT_F] fp32.
// ---------------------------------------------------------------------------
extern "C" void kernel_launch(void* const* d_in, const int* in_sizes, int n_in,
                              void* d_out, int out_size)
{
    const float* x = (const float*)d_in[0];
    const float* w = (const float*)d_in[1];
    float* out = (float*)d_out;

    scan_kernel<<<OUT_F / 8, 256>>>(w);
    out_kernel<<<M_ROWS / 8, 256>>>(x, out);
}